// round 10
// baseline (speedup 1.0000x reference)
#include <cuda_runtime.h>
#include <mma.h>
#include <math.h>

using namespace nvcuda;

#define D    1024
#define B    32
#define S    512
#define ND4  4096   // 4*D
#define NCTA 128    // scan CTAs; each owns 8 hidden dims (1 CTA/SM -> all resident)

// ---------------- device scratch (no cudaMalloc allowed) ----------------
__device__ float    g_U4[(size_t)D * ND4];        // 16 MB  [k][4D] packed input weights (tf32-rounded)
__device__ float    g_W4[(size_t)D * ND4];        // 16 MB  [k][4D] packed recurrent weights (tf32-rounded)
__device__ float    g_b4[ND4];                    // packed bias
__device__ float    g_Xr[(size_t)B * S * D];      // 64 MB  tf32-rounded copy of seq input
__device__ float    g_xproj[(size_t)S * B * ND4]; // 256 MB [s][b][4D]
__device__ float    g_h[2][B * D];                // double-buffered hidden state (tf32-rounded)
__device__ unsigned g_ctr;                        // grid barrier counter

// ---------------- math helpers (documented fast intrinsics only) ----------------
__device__ __forceinline__ float fast_sigmoid(float x) {
    return __fdividef(1.f, 1.f + __expf(-x));
}
__device__ __forceinline__ float fast_tanh(float x) {
    // (e^{2x}-1)/(e^{2x}+1); __expf <=6 ulp for |x|<~4 -> few-ulp tanh
    float t = __expf(2.f * x);
    return (t - 1.f) * __fdividef(1.f, t + 1.f);
}

// ---------------- cp.async helpers ----------------
__device__ __forceinline__ void cp16(void* smem_dst, const void* gsrc) {
    unsigned saddr = (unsigned)__cvta_generic_to_shared(smem_dst);
    asm volatile("cp.async.cg.shared.global [%0], [%1], 16;" :: "r"(saddr), "l"(gsrc));
}
__device__ __forceinline__ void cp_commit() { asm volatile("cp.async.commit_group;"); }
__device__ __forceinline__ void cp_wait1()  { asm volatile("cp.async.wait_group 1;"); }
__device__ __forceinline__ void cp_wait0()  { asm volatile("cp.async.wait_group 0;"); }

// ---------------- pack weights into fused [D,4D] layout (tf32-rounded) ----------------
__global__ void pack_kernel(const float* __restrict__ Ui, const float* __restrict__ Uf,
                            const float* __restrict__ Uo, const float* __restrict__ Ug,
                            const float* __restrict__ Wi, const float* __restrict__ Wf,
                            const float* __restrict__ Wo, const float* __restrict__ Wg,
                            const float* __restrict__ bi, const float* __restrict__ bf,
                            const float* __restrict__ bo, const float* __restrict__ bg) {
    long idx = (long)blockIdx.x * blockDim.x + threadIdx.x;
    if (idx >= (long)D * ND4) return;
    int k   = (int)(idx / ND4);
    int col = (int)(idx % ND4);
    int g   = col >> 10;       // gate index 0..3
    int e   = col & (D - 1);
    const float* Us[4] = {Ui, Uf, Uo, Ug};
    const float* Ws[4] = {Wi, Wf, Wo, Wg};
    // pre-round to tf32 so hot loops can skip per-fragment conversion
    g_U4[idx] = wmma::__float_to_tf32(Us[g][(long)k * D + e]);
    g_W4[idx] = wmma::__float_to_tf32(Ws[g][(long)k * D + e]);
    if (idx < ND4) {
        const float* bs[4] = {bi, bf, bo, bg};
        g_b4[idx] = bs[idx >> 10][idx & (D - 1)];
    }
}

// tf32-round the sequence input once; gemm1 then needs no per-fragment cvt
__global__ void round_kernel(const float* __restrict__ X) {
    long i = ((long)blockIdx.x * blockDim.x + threadIdx.x) * 4;
    if (i >= (long)B * S * D) return;
    float4 v = *(const float4*)(X + i);
    v.x = wmma::__float_to_tf32(v.x);
    v.y = wmma::__float_to_tf32(v.y);
    v.z = wmma::__float_to_tf32(v.z);
    v.w = wmma::__float_to_tf32(v.w);
    *(float4*)(g_Xr + i) = v;
}

__global__ void init_kernel() {
    int i = blockIdx.x * blockDim.x + threadIdx.x;
    if (i < B * D) {
        g_h[0][i] = 0.f;
        g_h[1][i] = 0.f;
    }
    if (i == 0) g_ctr = 0u;
}

// ---------------- GEMM1: xproj[s][b][e] = Xr[b*S+s][:] @ U4 ----------------
// CTA tile 128x128, BK=32, 3-stage cp.async pipeline, 2 CTAs/SM.
// 8 warps (4m x 2n), warp tile 32x64, wmma tf32 m16n16k8. Operands pre-rounded.
#define BM 128
#define BN 128
#define BK 32
#define A_LD 36       // As row stride (floats); 144B = 16B-aligned
#define B_LD 132      // Bs row stride (floats); 528B = 16B-aligned
#define STG_A (BM * A_LD)             // floats per A stage
#define STG_B (BK * B_LD)             // floats per B stage
#define STG   (STG_A + STG_B)
#define G1_SMEM_BYTES (3 * STG * 4)   // ~103.5 KB; fits 2 CTAs/SM (207 KB)

__global__ __launch_bounds__(256, 2) void gemm1_kernel() {
    extern __shared__ float g1s[];    // [3][STG]: As then Bs per stage

    const int bm  = blockIdx.y * BM;
    const int bn  = blockIdx.x * BN;
    const int tid = threadIdx.x;
    const int w   = tid >> 5;
    const int wm  = w & 3;
    const int wn  = w >> 2;

    const int NIT = D / BK;           // 32 K-stages

    // per-thread load coords (fixed across stages)
    const int ar[4] = { (tid) >> 3, (tid + 256) >> 3, (tid + 512) >> 3, (tid + 768) >> 3 };
    const int ac    = (tid & 7) << 2;
    const int br[4] = { (tid) >> 5, (tid + 256) >> 5, (tid + 512) >> 5, (tid + 768) >> 5 };
    const int bc    = (tid & 31) << 2;

    auto load_stage = [&](int st, int k0) {
        float* As = g1s + st * STG;
        float* Bs = As + STG_A;
#pragma unroll
        for (int i = 0; i < 4; i++)
            cp16(&As[ar[i] * A_LD + ac], g_Xr + (long)(bm + ar[i]) * D + k0 + ac);
#pragma unroll
        for (int i = 0; i < 4; i++)
            cp16(&Bs[br[i] * B_LD + bc], g_U4 + (long)(k0 + br[i]) * ND4 + bn + bc);
        cp_commit();
    };

    wmma::fragment<wmma::accumulator, 16, 16, 8, float> acc[2][4];
#pragma unroll
    for (int mi = 0; mi < 2; mi++)
#pragma unroll
        for (int ni = 0; ni < 4; ni++)
            wmma::fill_fragment(acc[mi][ni], 0.0f);

    load_stage(0, 0);
    load_stage(1, BK);

    for (int it = 0; it < NIT; it++) {
        // groups commit in stage order; newest committed group is it+1 except on the
        // tail where no more issues happen -> final iteration must drain fully.
        if (it == NIT - 1) cp_wait0(); else cp_wait1();
        __syncthreads();

        if (it + 2 < NIT) load_stage((it + 2) % 3, (it + 2) * BK);

        const float* As = g1s + (it % 3) * STG;
        const float* Bs = As + STG_A;

#pragma unroll
        for (int ks = 0; ks < BK; ks += 8) {
            wmma::fragment<wmma::matrix_a, 16, 16, 8, wmma::precision::tf32, wmma::row_major> af[2];
            wmma::fragment<wmma::matrix_b, 16, 16, 8, wmma::precision::tf32, wmma::row_major> bfg[4];
#pragma unroll
            for (int mi = 0; mi < 2; mi++)
                wmma::load_matrix_sync(af[mi], &As[(wm * 32 + mi * 16) * A_LD + ks], A_LD);
#pragma unroll
            for (int ni = 0; ni < 4; ni++)
                wmma::load_matrix_sync(bfg[ni], &Bs[ks * B_LD + wn * 64 + ni * 16], B_LD);
            // both operands pre-rounded to tf32 -> no cvt loops
#pragma unroll
            for (int mi = 0; mi < 2; mi++)
#pragma unroll
                for (int ni = 0; ni < 4; ni++)
                    wmma::mma_sync(acc[mi][ni], af[mi], bfg[ni], acc[mi][ni]);
        }
        __syncthreads();         // stage consumed; its buffer may be refilled next iter
    }

    // epilogue: remap row m=(b*512+s) -> xproj row (s*32+b); 16 consecutive m
    // stay inside one b (512%16==0) -> ldm = B*ND4.
#pragma unroll
    for (int mi = 0; mi < 2; mi++) {
#pragma unroll
        for (int ni = 0; ni < 4; ni++) {
            int m0 = bm + wm * 32 + mi * 16;
            int n0 = bn + wn * 64 + ni * 16;
            int b_ = m0 >> 9;
            int s0 = m0 & 511;
            float* p = g_xproj + ((long)s0 * B + b_) * ND4 + n0;
            wmma::store_matrix_sync(p, acc[mi][ni], B * ND4, wmma::mem_row_major);
        }
    }
}

// ---------------- persistent recurrent scan ----------------
// 128 CTAs, 1/SM (~186KB SMEM), all co-resident -> atomic grid barrier is safe.
// CTA j owns hidden dims [8j, 8j+8) for ALL 4 gates; its W slice (1024 x 32)
// lives in SMEM for the whole scan. Cell state: 1 value per thread, register.
// z tile per step: 32 (batch) x 32 (4 gates x 8 dims).
// 8 warps = (kh: K-chunk parity) x (mi: batch half) x (ni: z-col half).
// 4 accumulators per warp break the serial HMMA dependency chain (64 -> 4x16).

#define HCH   128                // h chunk (K) size -> 8 chunks/step
#define NCH   (D / HCH)          // 8
#define WS_LD 36                 // W smem row stride (floats)
#define HS_LD 132                // h smem row stride (HCH + 4)
#define ZP_LD 36                 // z partial stride
#define SCAN_SMEM_FLOATS (1024 * WS_LD + 2 * 32 * HS_LD + 2 * 32 * ZP_LD)
#define SCAN_SMEM_BYTES  (SCAN_SMEM_FLOATS * 4)   // ~186 KB

__device__ __forceinline__ void grid_barrier(int tid, unsigned target) {
    __threadfence();
    __syncthreads();
    if (tid == 0) {
        atomicAdd(&g_ctr, 1u);                 // arrive (atomic)
        while (*(volatile unsigned*)&g_ctr < target) __nanosleep(16);  // poll (plain L2 read)
        __threadfence();
    }
    __syncthreads();
}

__global__ __launch_bounds__(256, 1) void scan_kernel(float* __restrict__ out) {
    extern __shared__ float smem[];
    float* wsm = smem;                         // [1024][WS_LD]
    float* hsm = wsm + 1024 * WS_LD;           // [2][32][HS_LD]
    float* zp  = hsm + 2 * 32 * HS_LD;         // [2][32][ZP_LD]

    const int j    = blockIdx.x;
    const int hid0 = j * 8;
    const int tid  = threadIdx.x;
    const int w    = tid >> 5;
    const int kh   = w >> 2;          // K-chunk parity owned by this warp
    const int mi   = w & 1;           // batch half
    const int ni   = (w >> 1) & 1;    // z-col half

    // ---- preload W slice: rows k=0..1023, cols g*8+hh -> g_W4[k][g*1024+hid0+hh]
    for (int i = tid; i < 4096; i += 256) {   // 1024 rows x 4 gates
        int k = i >> 2, g = i & 3;
        const float4* src = (const float4*)(g_W4 + (long)k * ND4 + g * D + hid0);
        float* dst = &wsm[k * WS_LD + g * 8];
        *(float4*)dst       = src[0];
        *(float4*)(dst + 4) = src[1];
    }

    // ---- per-thread element: batch b, local dim hh
    const int b_  = tid >> 3;
    const int hh  = tid & 7;
    const int col = hid0 + hh;
    const float bi4[4] = { g_b4[col], g_b4[D + col], g_b4[2 * D + col], g_b4[3 * D + col] };
    float creg = 0.f;                 // cell state, register-resident

    // h-chunk load coords: 32 rows x HCH cols = 1024 float4, 4/thread
    const int hr[4] = { (tid) >> 5, (tid + 256) >> 5, (tid + 512) >> 5, (tid + 768) >> 5 };
    const int hc    = (tid & 31) << 2;

    __syncthreads();

    for (int s = 0; s < S; s++) {
        const float* __restrict__ hprev = g_h[s & 1];
        float* __restrict__ hnext       = g_h[(s + 1) & 1];
        const float* __restrict__ xp    = g_xproj + (long)s * B * ND4;

        // prefetch this step's xproj values; streaming hint (read-once data,
        // don't let 256MB of xproj churn the L2 working set)
        float x0 = __ldcs(&xp[(long)b_ * ND4 + col]);
        float x1 = __ldcs(&xp[(long)b_ * ND4 + D + col]);
        float x2 = __ldcs(&xp[(long)b_ * ND4 + 2 * D + col]);
        float x3 = __ldcs(&xp[(long)b_ * ND4 + 3 * D + col]);

        // 4 independent accumulators -> 4 short HMMA dependency chains
        wmma::fragment<wmma::accumulator, 16, 16, 8, float> acc[4];
#pragma unroll
        for (int a = 0; a < 4; a++)
            wmma::fill_fragment(acc[a], 0.0f);

        // preload h chunk 0 into buf 0
#pragma unroll
        for (int i = 0; i < 4; i++)
            *(float4*)&hsm[0 * 32 * HS_LD + hr[i] * HS_LD + hc] =
                *(const float4*)(hprev + hr[i] * D + hc);
        __syncthreads();

        // software-pipelined chunk loop: load ic+1 to regs, MMA ic (parity warps), store regs
        for (int ic = 0; ic < NCH; ic++) {
            const int buf = ic & 1;
            float4 p[4];
            if (ic < NCH - 1) {
                int kc = (ic + 1) * HCH;
#pragma unroll
                for (int i = 0; i < 4; i++)
                    p[i] = *(const float4*)(hprev + hr[i] * D + kc + hc);
            }
            if (kh == buf) {
                const int kc = ic * HCH;
#pragma unroll
                for (int ks = 0; ks < HCH; ks += 8) {
                    wmma::fragment<wmma::matrix_a, 16, 16, 8, wmma::precision::tf32, wmma::row_major> af;
                    wmma::fragment<wmma::matrix_b, 16, 16, 8, wmma::precision::tf32, wmma::row_major> bfr;
                    // both operands pre-rounded to tf32 -> no cvt loops
                    wmma::load_matrix_sync(af, &hsm[buf * 32 * HS_LD + (mi * 16) * HS_LD + ks], HS_LD);
                    wmma::load_matrix_sync(bfr, &wsm[(kc + ks) * WS_LD + ni * 16], WS_LD);
                    wmma::mma_sync(acc[(ks >> 3) & 3], af, bfr, acc[(ks >> 3) & 3]);
                }
            }
            if (ic < NCH - 1) {
                int nb = buf ^ 1;
#pragma unroll
                for (int i = 0; i < 4; i++)
                    *(float4*)&hsm[nb * 32 * HS_LD + hr[i] * HS_LD + hc] = p[i];
            }
            __syncthreads();
        }

        // combine the 4 partial accumulators (same fragment shape -> elementwise)
#pragma unroll
        for (int x = 0; x < acc[0].num_elements; x++)
            acc[0].x[x] += acc[1].x[x] + acc[2].x[x] + acc[3].x[x];

        // write z partials (kh halves), reduce in gate phase
        wmma::store_matrix_sync(&zp[kh * 32 * ZP_LD + (mi * 16) * ZP_LD + ni * 16],
                                acc[0], ZP_LD, wmma::mem_row_major);
        __syncthreads();

        // ---- gate math: 1 element per thread (b_, col)
        {
            float zi = zp[b_ * ZP_LD + 0 * 8 + hh] + zp[32 * ZP_LD + b_ * ZP_LD + 0 * 8 + hh] + x0 + bi4[0];
            float zf = zp[b_ * ZP_LD + 1 * 8 + hh] + zp[32 * ZP_LD + b_ * ZP_LD + 1 * 8 + hh] + x1 + bi4[1];
            float zo = zp[b_ * ZP_LD + 2 * 8 + hh] + zp[32 * ZP_LD + b_ * ZP_LD + 2 * 8 + hh] + x2 + bi4[2];
            float zg = zp[b_ * ZP_LD + 3 * 8 + hh] + zp[32 * ZP_LD + b_ * ZP_LD + 3 * 8 + hh] + x3 + bi4[3];

            float it = fast_sigmoid(zi);
            float ft = fast_sigmoid(zf);
            float ot = fast_sigmoid(zo);
            float gt = fast_tanh(zg);

            float ct = fast_sigmoid(ft * creg + it * gt);   // nonstandard sigmoid cell
            creg = ct;
            float ht = fast_tanh(ct) * ot;
            hnext[b_ * D + col] = wmma::__float_to_tf32(ht);  // recurrence operand, pre-rounded
            // output: written once, never re-read -> streaming store (evict-first)
            __stcs(&out[(long)b_ * S * D + (long)s * D + col], ht);
        }

        grid_barrier(tid, (unsigned)(NCTA * (s + 1)));
    }
}

// ---------------- launch ----------------
extern "C" void kernel_launch(void* const* d_in, const int* in_sizes, int n_in,
                              void* d_out, int out_size) {
    const float* seq = (const float*)d_in[0];

    // classify by element count: 8 DxD matrices (order Ui,Wi,Uf,Wf,Uo,Wo,Ug,Wg),
    // 4 biases (bi,bf,bo,bg)
    const float* mats[8];
    const float* biases[4];
    int nm = 0, nb = 0;
    for (int i = 1; i < n_in; i++) {
        if (in_sizes[i] == D * D) { if (nm < 8) mats[nm++] = (const float*)d_in[i]; }
        else                      { if (nb < 4) biases[nb++] = (const float*)d_in[i]; }
    }

    // unconditional (no static guards): idempotent, not stream ops -> capture-safe
    cudaFuncSetAttribute(scan_kernel, cudaFuncAttributeMaxDynamicSharedMemorySize,
                         SCAN_SMEM_BYTES);
    cudaFuncSetAttribute(gemm1_kernel, cudaFuncAttributeMaxDynamicSharedMemorySize,
                         G1_SMEM_BYTES);

    pack_kernel<<<((long)D * ND4 + 255) / 256, 256>>>(
        mats[0], mats[2], mats[4], mats[6],   // Ui, Uf, Uo, Ug
        mats[1], mats[3], mats[5], mats[7],   // Wi, Wf, Wo, Wg
        biases[0], biases[1], biases[2], biases[3]);

    round_kernel<<<((long)B * S * D / 4 + 255) / 256, 256>>>(seq);

    init_kernel<<<(B * D + 255) / 256, 256>>>();

    gemm1_kernel<<<dim3(ND4 / BN, (B * S) / BM), 256, G1_SMEM_BYTES>>>();

    scan_kernel<<<NCTA, 256, SCAN_SMEM_BYTES>>>((float*)d_out);
}

// round 14
// speedup vs baseline: 1.0406x; 1.0406x over previous
#include <cuda_runtime.h>
#include <mma.h>
#include <math.h>

using namespace nvcuda;

#define D    1024
#define B    32
#define S    512
#define ND4  4096   // 4*D
#define NCTA 128    // scan CTAs; each owns 8 hidden dims (1 CTA/SM -> all resident)

// ---------------- device scratch (no cudaMalloc allowed) ----------------
__device__ float    g_U4[(size_t)D * ND4];        // 16 MB  [k][4D] packed input weights (tf32-rounded)
__device__ float    g_W4[(size_t)D * ND4];        // 16 MB  [k][4D] packed recurrent weights (tf32-rounded)
__device__ float    g_b4[ND4];                    // packed bias
__device__ float    g_Xr[(size_t)B * S * D];      // 64 MB  tf32-rounded copy of seq input
__device__ float    g_xproj[(size_t)S * B * ND4]; // 256 MB [s][b][4D]
__device__ float    g_h[2][B * D];                // double-buffered hidden state (tf32-rounded)
__device__ unsigned g_ctr;                        // grid barrier counter

// ---------------- math helpers (documented fast intrinsics only) ----------------
__device__ __forceinline__ float fast_sigmoid(float x) {
    return __fdividef(1.f, 1.f + __expf(-x));
}
__device__ __forceinline__ float fast_tanh(float x) {
    float t = __expf(2.f * x);
    return (t - 1.f) * __fdividef(1.f, t + 1.f);
}

// ---------------- cp.async helpers ----------------
__device__ __forceinline__ void cp16(void* smem_dst, const void* gsrc) {
    unsigned saddr = (unsigned)__cvta_generic_to_shared(smem_dst);
    asm volatile("cp.async.cg.shared.global [%0], [%1], 16;" :: "r"(saddr), "l"(gsrc));
}
__device__ __forceinline__ void cp_commit() { asm volatile("cp.async.commit_group;"); }
__device__ __forceinline__ void cp_wait2()  { asm volatile("cp.async.wait_group 2;"); }
__device__ __forceinline__ void cp_wait1()  { asm volatile("cp.async.wait_group 1;"); }
__device__ __forceinline__ void cp_wait0()  { asm volatile("cp.async.wait_group 0;"); }

// ---------------- pack weights into fused [D,4D] layout (tf32-rounded) ----------------
__global__ void pack_kernel(const float* __restrict__ Ui, const float* __restrict__ Uf,
                            const float* __restrict__ Uo, const float* __restrict__ Ug,
                            const float* __restrict__ Wi, const float* __restrict__ Wf,
                            const float* __restrict__ Wo, const float* __restrict__ Wg,
                            const float* __restrict__ bi, const float* __restrict__ bf,
                            const float* __restrict__ bo, const float* __restrict__ bg) {
    long idx = (long)blockIdx.x * blockDim.x + threadIdx.x;
    if (idx >= (long)D * ND4) return;
    int k   = (int)(idx / ND4);
    int col = (int)(idx % ND4);
    int g   = col >> 10;
    int e   = col & (D - 1);
    const float* Us[4] = {Ui, Uf, Uo, Ug};
    const float* Ws[4] = {Wi, Wf, Wo, Wg};
    g_U4[idx] = wmma::__float_to_tf32(Us[g][(long)k * D + e]);
    g_W4[idx] = wmma::__float_to_tf32(Ws[g][(long)k * D + e]);
    if (idx < ND4) {
        const float* bs[4] = {bi, bf, bo, bg};
        g_b4[idx] = bs[idx >> 10][idx & (D - 1)];
    }
}

// tf32-round the sequence input once; gemm1 then needs no per-fragment cvt
__global__ void round_kernel(const float* __restrict__ X) {
    long i = ((long)blockIdx.x * blockDim.x + threadIdx.x) * 4;
    if (i >= (long)B * S * D) return;
    float4 v = *(const float4*)(X + i);
    v.x = wmma::__float_to_tf32(v.x);
    v.y = wmma::__float_to_tf32(v.y);
    v.z = wmma::__float_to_tf32(v.z);
    v.w = wmma::__float_to_tf32(v.w);
    *(float4*)(g_Xr + i) = v;
}

__global__ void init_kernel() {
    int i = blockIdx.x * blockDim.x + threadIdx.x;
    if (i < B * D) {
        g_h[0][i] = 0.f;
        g_h[1][i] = 0.f;
    }
    if (i == 0) g_ctr = 0u;
}

// ---------------- GEMM1: xproj[s][b][e] = Xr[b*S+s][:] @ U4 ----------------
#define BM 128
#define BN 128
#define BK 32
#define A_LD 36
#define B_LD 132
#define STG_A (BM * A_LD)
#define STG_B (BK * B_LD)
#define STG   (STG_A + STG_B)
#define G1_SMEM_BYTES (3 * STG * 4)   // ~103.5 KB; fits 2 CTAs/SM

__global__ __launch_bounds__(256, 2) void gemm1_kernel() {
    extern __shared__ float g1s[];

    const int bm  = blockIdx.y * BM;
    const int bn  = blockIdx.x * BN;
    const int tid = threadIdx.x;
    const int w   = tid >> 5;
    const int wm  = w & 3;
    const int wn  = w >> 2;

    const int NIT = D / BK;

    const int ar[4] = { (tid) >> 3, (tid + 256) >> 3, (tid + 512) >> 3, (tid + 768) >> 3 };
    const int ac    = (tid & 7) << 2;
    const int br[4] = { (tid) >> 5, (tid + 256) >> 5, (tid + 512) >> 5, (tid + 768) >> 5 };
    const int bc    = (tid & 31) << 2;

    auto load_stage = [&](int st, int k0) {
        float* As = g1s + st * STG;
        float* Bs = As + STG_A;
#pragma unroll
        for (int i = 0; i < 4; i++)
            cp16(&As[ar[i] * A_LD + ac], g_Xr + (long)(bm + ar[i]) * D + k0 + ac);
#pragma unroll
        for (int i = 0; i < 4; i++)
            cp16(&Bs[br[i] * B_LD + bc], g_U4 + (long)(k0 + br[i]) * ND4 + bn + bc);
        cp_commit();
    };

    wmma::fragment<wmma::accumulator, 16, 16, 8, float> acc[2][4];
#pragma unroll
    for (int mi = 0; mi < 2; mi++)
#pragma unroll
        for (int ni = 0; ni < 4; ni++)
            wmma::fill_fragment(acc[mi][ni], 0.0f);

    load_stage(0, 0);
    load_stage(1, BK);

    for (int it = 0; it < NIT; it++) {
        if (it == NIT - 1) cp_wait0(); else cp_wait1();
        __syncthreads();

        if (it + 2 < NIT) load_stage((it + 2) % 3, (it + 2) * BK);

        const float* As = g1s + (it % 3) * STG;
        const float* Bs = As + STG_A;

#pragma unroll
        for (int ks = 0; ks < BK; ks += 8) {
            wmma::fragment<wmma::matrix_a, 16, 16, 8, wmma::precision::tf32, wmma::row_major> af[2];
            wmma::fragment<wmma::matrix_b, 16, 16, 8, wmma::precision::tf32, wmma::row_major> bfg[4];
#pragma unroll
            for (int mi = 0; mi < 2; mi++)
                wmma::load_matrix_sync(af[mi], &As[(wm * 32 + mi * 16) * A_LD + ks], A_LD);
#pragma unroll
            for (int ni = 0; ni < 4; ni++)
                wmma::load_matrix_sync(bfg[ni], &Bs[ks * B_LD + wn * 64 + ni * 16], B_LD);
#pragma unroll
            for (int mi = 0; mi < 2; mi++)
#pragma unroll
                for (int ni = 0; ni < 4; ni++)
                    wmma::mma_sync(acc[mi][ni], af[mi], bfg[ni], acc[mi][ni]);
        }
        __syncthreads();
    }

#pragma unroll
    for (int mi = 0; mi < 2; mi++) {
#pragma unroll
        for (int ni = 0; ni < 4; ni++) {
            int m0 = bm + wm * 32 + mi * 16;
            int n0 = bn + wn * 64 + ni * 16;
            int b_ = m0 >> 9;
            int s0 = m0 & 511;
            float* p = g_xproj + ((long)s0 * B + b_) * ND4 + n0;
            wmma::store_matrix_sync(p, acc[mi][ni], B * ND4, wmma::mem_row_major);
        }
    }
}

// ---------------- persistent recurrent scan ----------------
// h chunks flow through a 4-stage cp.async ring (2-3 chunks of lookahead)
// to cover queued-L2 latency. ONE sync per chunk iteration: passing the top
// sync of iter ic proves all threads finished iter ic-1's MMA, so refilling
// slot (ic+3)&3 == (ic-1)&3 after it is race-free. zp visibility for the
// gate phase is provided by a single post-loop sync.
#define HCH   128                // h chunk (K) size -> 8 chunks/step
#define NCH   (D / HCH)          // 8
#define NSTG  4                  // h ring stages
#define WS_LD 36
#define HS_LD 132
#define ZP_LD 36
#define SCAN_SMEM_FLOATS (1024 * WS_LD + NSTG * 32 * HS_LD + 2 * 32 * ZP_LD)
#define SCAN_SMEM_BYTES  (SCAN_SMEM_FLOATS * 4)   // 224,256 B

// cooperative-groups-style grid barrier: release-arrive + acquire-poll.
// No __threadfence -> no MEMBAR.GPU / CCTL.IVALL (L1 flush) per step.
__device__ __forceinline__ void grid_barrier(int tid, unsigned target) {
    __syncthreads();                     // all CTA work (incl. hnext stores) done
    if (tid == 0) {
        asm volatile("red.release.gpu.global.add.u32 [%0], %1;"
                     :: "l"(&g_ctr), "r"(1u) : "memory");
        unsigned v;
        while (true) {
            asm volatile("ld.acquire.gpu.global.u32 %0, [%1];"
                         : "=r"(v) : "l"(&g_ctr) : "memory");
            if (v >= target) break;
            __nanosleep(32);
        }
    }
    __syncthreads();                     // broadcast release within CTA
}

__global__ __launch_bounds__(256, 1) void scan_kernel(float* __restrict__ out) {
    extern __shared__ float smem[];
    float* wsm = smem;                          // [1024][WS_LD]
    float* hsm = wsm + 1024 * WS_LD;            // [NSTG][32][HS_LD]
    float* zp  = hsm + NSTG * 32 * HS_LD;       // [2][32][ZP_LD]

    const int j    = blockIdx.x;
    const int hid0 = j * 8;
    const int tid  = threadIdx.x;
    const int w    = tid >> 5;
    const int kh   = w >> 2;          // K-chunk parity owned by this warp
    const int mi   = w & 1;           // batch half
    const int ni   = (w >> 1) & 1;    // z-col half

    // ---- preload W slice (resident all scan)
    for (int i = tid; i < 4096; i += 256) {
        int k = i >> 2, g = i & 3;
        const float4* src = (const float4*)(g_W4 + (long)k * ND4 + g * D + hid0);
        float* dst = &wsm[k * WS_LD + g * 8];
        *(float4*)dst       = src[0];
        *(float4*)(dst + 4) = src[1];
    }

    const int b_  = tid >> 3;
    const int hh  = tid & 7;
    const int col = hid0 + hh;
    const float bi4[4] = { g_b4[col], g_b4[D + col], g_b4[2 * D + col], g_b4[3 * D + col] };
    float creg = 0.f;

    // h-chunk load coords: 32 rows x HCH cols = 1024 float4, 4/thread
    const int hr[4] = { (tid) >> 5, (tid + 256) >> 5, (tid + 512) >> 5, (tid + 768) >> 5 };
    const int hc    = (tid & 31) << 2;

    __syncthreads();

    for (int s = 0; s < S; s++) {
        const float* __restrict__ hprev = g_h[s & 1];
        float* __restrict__ hnext       = g_h[(s + 1) & 1];
        const float* __restrict__ xp    = g_xproj + (long)s * B * ND4;

        // prefetch xproj (streaming; hidden behind the chunk loop)
        float x0 = __ldcs(&xp[(long)b_ * ND4 + col]);
        float x1 = __ldcs(&xp[(long)b_ * ND4 + D + col]);
        float x2 = __ldcs(&xp[(long)b_ * ND4 + 2 * D + col]);
        float x3 = __ldcs(&xp[(long)b_ * ND4 + 3 * D + col]);

        wmma::fragment<wmma::accumulator, 16, 16, 8, float> acc[4];
#pragma unroll
        for (int a = 0; a < 4; a++)
            wmma::fill_fragment(acc[a], 0.0f);

        auto issue_hchunk = [&](int chk) {
            float* dstb = hsm + (chk & (NSTG - 1)) * 32 * HS_LD;
            const int kc = chk * HCH;
#pragma unroll
            for (int i = 0; i < 4; i++)
                cp16(&dstb[hr[i] * HS_LD + hc], hprev + hr[i] * D + kc + hc);
            cp_commit();
        };

        // prime the ring with 3 chunks
        issue_hchunk(0);
        issue_hchunk(1);
        issue_hchunk(2);

        for (int ic = 0; ic < NCH; ic++) {
            // wait for chunk ic (groups complete in issue order)
            if (ic < NCH - 2)      cp_wait2();
            else if (ic == NCH - 2) cp_wait1();
            else                    cp_wait0();
            __syncthreads();   // chunk ic visible to all; proves iter ic-1 MMAs done

            // refill: chunk ic+3 reuses chunk ic-1's slot (safe per top-sync argument)
            if (ic + 3 < NCH) issue_hchunk(ic + 3);

            if (kh == (ic & 1)) {
                const float* hb = hsm + (ic & (NSTG - 1)) * 32 * HS_LD;
                const int kc = ic * HCH;
#pragma unroll
                for (int ks = 0; ks < HCH; ks += 8) {
                    wmma::fragment<wmma::matrix_a, 16, 16, 8, wmma::precision::tf32, wmma::row_major> af;
                    wmma::fragment<wmma::matrix_b, 16, 16, 8, wmma::precision::tf32, wmma::row_major> bfr;
                    wmma::load_matrix_sync(af, &hb[(mi * 16) * HS_LD + ks], HS_LD);
                    wmma::load_matrix_sync(bfr, &wsm[(kc + ks) * WS_LD + ni * 16], WS_LD);
                    wmma::mma_sync(acc[(ks >> 3) & 3], af, bfr, acc[(ks >> 3) & 3]);
                }
                // after this warp's LAST chunk: combine accs + store z partial
                if (ic == NCH - 2 + kh) {
#pragma unroll
                    for (int x = 0; x < acc[0].num_elements; x++)
                        acc[0].x[x] += acc[1].x[x] + acc[2].x[x] + acc[3].x[x];
                    wmma::store_matrix_sync(&zp[kh * 32 * ZP_LD + (mi * 16) * ZP_LD + ni * 16],
                                            acc[0], ZP_LD, wmma::mem_row_major);
                }
            }
        }
        __syncthreads();       // zp partials visible to gate phase

        // ---- gate math: 1 element per thread (b_, col)
        {
            float zi = zp[b_ * ZP_LD + 0 * 8 + hh] + zp[32 * ZP_LD + b_ * ZP_LD + 0 * 8 + hh] + x0 + bi4[0];
            float zf = zp[b_ * ZP_LD + 1 * 8 + hh] + zp[32 * ZP_LD + b_ * ZP_LD + 1 * 8 + hh] + x1 + bi4[1];
            float zo = zp[b_ * ZP_LD + 2 * 8 + hh] + zp[32 * ZP_LD + b_ * ZP_LD + 2 * 8 + hh] + x2 + bi4[2];
            float zg = zp[b_ * ZP_LD + 3 * 8 + hh] + zp[32 * ZP_LD + b_ * ZP_LD + 3 * 8 + hh] + x3 + bi4[3];

            float it = fast_sigmoid(zi);
            float ft = fast_sigmoid(zf);
            float ot = fast_sigmoid(zo);
            float gt = fast_tanh(zg);

            float ct = fast_sigmoid(ft * creg + it * gt);   // nonstandard sigmoid cell
            creg = ct;
            float ht = fast_tanh(ct) * ot;
            hnext[b_ * D + col] = wmma::__float_to_tf32(ht);
            __stcs(&out[(long)b_ * S * D + (long)s * D + col], ht);
        }

        grid_barrier(tid, (unsigned)(NCTA * (s + 1)));
    }
}

// ---------------- launch ----------------
extern "C" void kernel_launch(void* const* d_in, const int* in_sizes, int n_in,
                              void* d_out, int out_size) {
    const float* seq = (const float*)d_in[0];

    const float* mats[8];
    const float* biases[4];
    int nm = 0, nb = 0;
    for (int i = 1; i < n_in; i++) {
        if (in_sizes[i] == D * D) { if (nm < 8) mats[nm++] = (const float*)d_in[i]; }
        else                      { if (nb < 4) biases[nb++] = (const float*)d_in[i]; }
    }

    cudaFuncSetAttribute(scan_kernel, cudaFuncAttributeMaxDynamicSharedMemorySize,
                         SCAN_SMEM_BYTES);
    cudaFuncSetAttribute(gemm1_kernel, cudaFuncAttributeMaxDynamicSharedMemorySize,
                         G1_SMEM_BYTES);

    pack_kernel<<<((long)D * ND4 + 255) / 256, 256>>>(
        mats[0], mats[2], mats[4], mats[6],   // Ui, Uf, Uo, Ug
        mats[1], mats[3], mats[5], mats[7],   // Wi, Wf, Wo, Wg
        biases[0], biases[1], biases[2], biases[3]);

    round_kernel<<<((long)B * S * D / 4 + 255) / 256, 256>>>(seq);

    init_kernel<<<(B * D + 255) / 256, 256>>>();

    gemm1_kernel<<<dim3(ND4 / BN, (B * S) / BM), 256, G1_SMEM_BYTES>>>();

    scan_kernel<<<NCTA, 256, SCAN_SMEM_BYTES>>>((float*)d_out);
}